// round 11
// baseline (speedup 1.0000x reference)
#include <cuda_runtime.h>
#include <cuda_bf16.h>
#include <cstdint>

#define NN 8192
#define FF 256

// ---- device scratch ----
__device__ __align__(16) float g_E[NN * FF];             // emb after iter0 (fp32)
__device__ __align__(16) __nv_bfloat16 g_Yt[FF * NN];    // Y^T bf16 (iter0 only)
__device__ __align__(16) float g_Gp[8 * FF * FF];        // SYRK split-K partials (2MB)
__device__ __align__(16) __nv_bfloat16 g_Gh[FF * FF];    // Gram bf16 (iter0)
__device__ __align__(16) float g_s[2 * FF];              // colsum(Y) per iter
__device__ __align__(16) float g_gs[FF];                 // gs = G1 s1 accum (iter1)
__device__ float g_r[NN];                                // per-row sumsq (iter0)
__device__ float g_rp[2 * NN];                           // per-row sumsq partials (iter1)
__device__ float g_alpha[NN];                            // per-row scale (alpha0 then alpha1)
__device__ float g_d[NN];                                // w_j (iter1)
__device__ float g_Tp1[1024];                            // T partials iter0
__device__ float g_Tp2[128];                             // T partials iter1
__device__ float g_ab[4];                                // a0,b0,a1,b1

// ---- mma / ldmatrix helpers ----
__device__ __forceinline__ uint32_t smem_u32(const void* p) {
    return (uint32_t)__cvta_generic_to_shared(p);
}
__device__ __forceinline__ void ldsm4(uint32_t (&r)[4], uint32_t addr) {
    asm volatile("ldmatrix.sync.aligned.m8n8.x4.shared.b16 {%0,%1,%2,%3}, [%4];"
                 : "=r"(r[0]), "=r"(r[1]), "=r"(r[2]), "=r"(r[3]) : "r"(addr));
}
__device__ __forceinline__ void ldsm4t(uint32_t (&r)[4], uint32_t addr) {
    asm volatile("ldmatrix.sync.aligned.m8n8.x4.trans.shared.b16 {%0,%1,%2,%3}, [%4];"
                 : "=r"(r[0]), "=r"(r[1]), "=r"(r[2]), "=r"(r[3]) : "r"(addr));
}
__device__ __forceinline__ void mma16816(float* c, const uint32_t* a, uint32_t b0, uint32_t b1) {
    asm volatile("mma.sync.aligned.m16n8k16.row.col.f32.bf16.bf16.f32 "
                 "{%0,%1,%2,%3}, {%4,%5,%6,%7}, {%8,%9}, {%0,%1,%2,%3};"
                 : "+f"(c[0]), "+f"(c[1]), "+f"(c[2]), "+f"(c[3])
                 : "r"(a[0]), "r"(a[1]), "r"(a[2]), "r"(a[3]), "r"(b0), "r"(b1));
}

// ---- K0: rownorm partials (blocks 0..1023) + scalars/zeroing (block 1024) ----
__global__ void k_init(const float* __restrict__ X,
                       const float* __restrict__ linear,
                       const float* __restrict__ dirv,
                       const float* __restrict__ feat) {
    int t = threadIdx.x;
    if (blockIdx.x == 1024) {
        g_s[t] = 0.f; g_s[FF + t] = 0.f; g_gs[t] = 0.f;
        __shared__ float red[256];
        for (int i = 0; i < 2; i++) {
            float pa = feat[i * FF + t] * linear[i * FF + t];
            float pb = dirv[i * FF + t] * linear[i * FF + t];
            red[t] = pa; __syncthreads();
            for (int o = 128; o > 0; o >>= 1) { if (t < o) red[t] += red[t + o]; __syncthreads(); }
            if (t == 0) g_ab[2 * i] = red[0];
            __syncthreads();
            red[t] = pb; __syncthreads();
            for (int o = 128; o > 0; o >>= 1) { if (t < o) red[t] += red[t + o]; __syncthreads(); }
            if (t == 0) g_ab[2 * i + 1] = red[0];
            __syncthreads();
        }
        return;
    }
    int warp = t >> 5, lane = t & 31;
    int row = blockIdx.x * 8 + warp;
    const float* xr = X + row * FF;
    float s = 0.f;
#pragma unroll
    for (int u = 0; u < 8; u++) { float v = xr[lane + 32 * u]; s += v * v; }
#pragma unroll
    for (int o = 16; o > 0; o >>= 1) s += __shfl_xor_sync(0xffffffffu, s, o);
    __shared__ float ws[8];
    if (lane == 0) { ws[warp] = s; g_r[row] = s; }
    __syncthreads();
    if (t == 0) {
        float tt = 0.f;
        for (int w = 0; w < 8; w++) tt += ws[w];
        g_Tp1[blockIdx.x] = tt;
    }
}

// ---- prep (iter0): T reduce + alpha0 inline; Yt = bf16(alpha0*X); colsum s0 ----
__global__ void k_prep(const float* __restrict__ src) {
    __shared__ float red[256];
    __shared__ float sh[64][65];
    __shared__ float csm[64];
    int t = threadIdx.x;
    float tacc = 0.f;
    for (int i = t; i < 1024; i += 256) tacc += g_Tp1[i];
    red[t] = tacc; __syncthreads();
    for (int o = 128; o > 0; o >>= 1) { if (t < o) red[t] += red[t + o]; __syncthreads(); }
    float T = red[0];
    __syncthreads();

    float a = g_ab[0], bb = g_ab[1];
    float nf = sqrtf(T);
    float sb = (bb >= 0.f) ? 1.f : -1.f;

    int jt = blockIdx.x >> 2;
    int cb = (blockIdx.x & 3) * 64;
    int j0 = jt * 64;
    if (t < 64) csm[t] = 0.f;
    __syncthreads();
    int lr = t >> 4, lc = (t & 15) * 4;
    float ca0 = 0, ca1 = 0, ca2 = 0, ca3 = 0;
#pragma unroll
    for (int w = 0; w < 4; w++) {
        int row = lr + w * 16;
        int J = j0 + row;
        float inner = a * sb * g_r[J] / nf;
        float scale = (inner <= 0.f) ? inner : 0.f;
        float al = a - scale * sb / nf;
        if ((blockIdx.x & 3) == 0 && (t & 15) == 0) g_alpha[J] = al;
        float4 v = *(const float4*)&src[J * FF + cb + lc];
        float y0 = al * v.x, y1 = al * v.y, y2 = al * v.z, y3 = al * v.w;
        sh[row][lc] = y0; sh[row][lc + 1] = y1; sh[row][lc + 2] = y2; sh[row][lc + 3] = y3;
        ca0 += y0; ca1 += y1; ca2 += y2; ca3 += y3;
    }
    atomicAdd(&csm[lc], ca0); atomicAdd(&csm[lc + 1], ca1);
    atomicAdd(&csm[lc + 2], ca2); atomicAdd(&csm[lc + 3], ca3);
    __syncthreads();
    int cl = t >> 4, jl = (t & 15) * 4;
#pragma unroll
    for (int w = 0; w < 4; w++) {
        int c = cl + w * 16;
        __nv_bfloat16 p[4];
        p[0] = __float2bfloat16(sh[jl + 0][c]);
        p[1] = __float2bfloat16(sh[jl + 1][c]);
        p[2] = __float2bfloat16(sh[jl + 2][c]);
        p[3] = __float2bfloat16(sh[jl + 3][c]);
        *(uint2*)&g_Yt[(cb + c) * NN + j0 + jl] = *(uint2*)p;
    }
    if (t < 64) atomicAdd(&g_s[cb + t], csm[t]);
}

// ---- SYRK: 64x64 G-tiles x 8 K-chunks of 1024 rows; grid (16,8) = 128 CTAs ----
__global__ __launch_bounds__(256, 2) void k_syrk() {
    __shared__ __nv_bfloat16 Ash[64][72];
    __shared__ __nv_bfloat16 Bsh[64][72];
    int t = threadIdx.x, lane = t & 31, w = t >> 5;
    int wm = w >> 2, wn = w & 3;              // 2x4 warps -> warp tile 32x16
    int ta = blockIdx.x >> 2, tb = blockIdx.x & 3;
    int j0 = blockIdx.y * 1024;
    float acc[2][2][4];
#pragma unroll
    for (int i = 0; i < 2; i++)
#pragma unroll
        for (int j = 0; j < 2; j++)
#pragma unroll
            for (int q = 0; q < 4; q++) acc[i][j][q] = 0.f;

    for (int ks = 0; ks < 16; ks++) {
        __syncthreads();
#pragma unroll
        for (int u = 0; u < 2; u++) {
            int idx = t + u * 256;
            int row = idx >> 3, g = idx & 7;
            *(uint4*)&Ash[row][g * 8] = *(const uint4*)&g_Yt[(ta * 64 + row) * NN + j0 + ks * 64 + g * 8];
            *(uint4*)&Bsh[row][g * 8] = *(const uint4*)&g_Yt[(tb * 64 + row) * NN + j0 + ks * 64 + g * 8];
        }
        __syncthreads();
#pragma unroll
        for (int kk = 0; kk < 4; kk++) {
            uint32_t a[2][4], b[4];
#pragma unroll
            for (int mi = 0; mi < 2; mi++) {
                int row = wm * 32 + mi * 16 + (lane & 15);
                int col = kk * 16 + 8 * (lane >> 4);
                ldsm4(a[mi], smem_u32(&Ash[row][col]));
            }
            {
                int g = lane >> 3;
                int row = wn * 16 + 8 * (g >> 1) + (lane & 7);
                int col = kk * 16 + 8 * (g & 1);
                ldsm4(b, smem_u32(&Bsh[row][col]));
            }
#pragma unroll
            for (int mi = 0; mi < 2; mi++)
#pragma unroll
                for (int nj = 0; nj < 2; nj++)
                    mma16816(acc[mi][nj], a[mi], b[nj * 2], b[nj * 2 + 1]);
        }
    }
    float* gp = &g_Gp[blockIdx.y * (FF * FF)];
#pragma unroll
    for (int mi = 0; mi < 2; mi++)
#pragma unroll
        for (int nj = 0; nj < 2; nj++)
#pragma unroll
            for (int gi = 0; gi < 2; gi++) {
                int row = ta * 64 + wm * 32 + mi * 16 + (lane >> 2) + 8 * gi;
                int col = tb * 64 + wn * 16 + nj * 8 + (lane & 3) * 2;
                *(float2*)&gp[row * FF + col] = make_float2(acc[mi][nj][2 * gi], acc[mi][nj][2 * gi + 1]);
            }
}

// ---- Gp reduce -> Gh; grid 1024, 4 threads per output x 2 chunks each ----
__global__ void k_gred() {
    int t = threadIdx.x, b = blockIdx.x;
    int i = b * 64 + (t >> 2);
    int ch0 = t & 3;
    float sum = g_Gp[ch0 * (FF * FF) + i] + g_Gp[(ch0 + 4) * (FF * FF) + i];
    sum += __shfl_xor_sync(0xffffffffu, sum, 1);
    sum += __shfl_xor_sync(0xffffffffu, sum, 2);
    if ((t & 3) == 0) g_Gh[i] = __float2bfloat16(sum);
}

// ---- update (iter0): E = y + (Y.Gh - d*y)/N; d = Y.s in-loop; r/T partials ----
__global__ __launch_bounds__(256, 2) void k_update(const float* __restrict__ src) {
    __shared__ __nv_bfloat16 Ysh[16][136];
    __shared__ __nv_bfloat16 Gsh[128][24];
    __shared__ float s_sh[FF];
    __shared__ float dps[256];
    __shared__ float rsm[128];
    int t = threadIdx.x, lane = t & 31, w = t >> 5;
    int wm = w >> 2, wn = w & 3;
    int rt = blockIdx.x >> 1, ct = blockIdx.x & 1;
    int rowbase = rt * 128, colbase = ct * 128;
    if (t < 128) rsm[t] = 0.f;
    s_sh[t] = g_s[t];
    float dpart = 0.f;
    int dj = t & 127, dhalf = t >> 7;
    float acc[4][4][4];
#pragma unroll
    for (int i = 0; i < 4; i++)
#pragma unroll
        for (int j = 0; j < 4; j++)
#pragma unroll
            for (int q = 0; q < 4; q++) acc[i][j][q] = 0.f;

    for (int kk = 0; kk < 16; kk++) {
        __syncthreads();
        {
            int row = t >> 4, g = t & 15;
            *(uint4*)&Ysh[row][g * 8] = *(const uint4*)&g_Yt[(kk * 16 + row) * NN + rowbase + g * 8];
        }
        {
            int n = t >> 1, g = t & 1;
            *(uint4*)&Gsh[n][g * 8] = *(const uint4*)&g_Gh[(colbase + n) * FF + kk * 16 + g * 8];
        }
        __syncthreads();
#pragma unroll
        for (int ff = 0; ff < 8; ff++) {
            int f = dhalf * 8 + ff;
            dpart += __bfloat162float(Ysh[f][dj]) * s_sh[kk * 16 + f];
        }
        uint32_t a[4][4], b[2][4];
#pragma unroll
        for (int mi = 0; mi < 4; mi++) {
            int krow = (lane & 7) + 8 * ((lane >> 4) & 1);
            int mcol = wm * 64 + mi * 16 + 8 * ((lane >> 3) & 1);
            ldsm4t(a[mi], smem_u32(&Ysh[krow][mcol]));
        }
#pragma unroll
        for (int p = 0; p < 2; p++) {
            int g = lane >> 3;
            int row = wn * 32 + p * 16 + 8 * (g >> 1) + (lane & 7);
            int col = 8 * (g & 1);
            ldsm4(b[p], smem_u32(&Gsh[row][col]));
        }
#pragma unroll
        for (int mi = 0; mi < 4; mi++)
#pragma unroll
            for (int nj = 0; nj < 4; nj++)
                mma16816(acc[mi][nj], a[mi], b[nj >> 1][(nj & 1) * 2], b[nj >> 1][(nj & 1) * 2 + 1]);
    }
    dps[t] = dpart;
    __syncthreads();

    const float inv = 1.0f / (float)NN;
    float rowsq[4][2];
#pragma unroll
    for (int i = 0; i < 4; i++) { rowsq[i][0] = 0.f; rowsq[i][1] = 0.f; }

#pragma unroll
    for (int mi = 0; mi < 4; mi++)
#pragma unroll
        for (int gi = 0; gi < 2; gi++) {
            int r = wm * 64 + mi * 16 + (lane >> 2) + 8 * gi;
            int Rg = rowbase + r;
            float al = g_alpha[Rg];
            float dd = dps[r] + dps[r + 128];
#pragma unroll
            for (int nj = 0; nj < 4; nj++) {
                int c = colbase + wn * 32 + nj * 8 + (lane & 3) * 2;
                float2 v = *(const float2*)&src[Rg * FF + c];
                float y0 = al * v.x, y1 = al * v.y;
                float e0 = y0 + (acc[mi][nj][2 * gi] - dd * y0) * inv;
                float e1 = y1 + (acc[mi][nj][2 * gi + 1] - dd * y1) * inv;
                *(float2*)&g_E[Rg * FF + c] = make_float2(e0, e1);
                rowsq[mi][gi] += e0 * e0 + e1 * e1;
            }
        }
#pragma unroll
    for (int mi = 0; mi < 4; mi++)
#pragma unroll
        for (int gi = 0; gi < 2; gi++) {
            float v = rowsq[mi][gi];
            v += __shfl_xor_sync(0xffffffffu, v, 1);
            v += __shfl_xor_sync(0xffffffffu, v, 2);
            if ((lane & 3) == 0) atomicAdd(&rsm[wm * 64 + mi * 16 + (lane >> 2) + 8 * gi], v);
        }
    __syncthreads();
    if (t < 128) g_rp[ct * NN + rowbase + t] = rsm[t];
    if (t == 0) {
        float tt = 0.f;
        for (int i = 0; i < 128; i++) tt += rsm[i];
        g_Tp2[blockIdx.x] = tt;
    }
}

// ---- iter1 pass 1: alpha1 + s1 = colsum(alpha1 . E) ----
__global__ void k_s1() {
    __shared__ float red[256];
    __shared__ float ash[64];
    int t = threadIdx.x;
    float tacc = (t < 128) ? g_Tp2[t] : 0.f;
    red[t] = tacc; __syncthreads();
    for (int o = 128; o > 0; o >>= 1) { if (t < o) red[t] += red[t + o]; __syncthreads(); }
    float T = red[0];
    float a = g_ab[2], bb = g_ab[3];
    float nf = sqrtf(T);
    float sb = (bb >= 0.f) ? 1.f : -1.f;
    int rowbase = blockIdx.x * 64;
    if (t < 64) {
        int J = rowbase + t;
        float rJ = g_rp[J] + g_rp[NN + J];
        float inner = a * sb * rJ / nf;
        float scale = (inner <= 0.f) ? inner : 0.f;
        float al = a - scale * sb / nf;
        g_alpha[J] = al;
        ash[t] = al;
    }
    __syncthreads();
    float cs = 0.f;
#pragma unroll 4
    for (int j = 0; j < 64; j++)
        cs += ash[j] * g_E[(rowbase + j) * FF + t];
    atomicAdd(&g_s[FF + t], cs);
}

// ---- iter1 pass 2: w_j = alpha_j (E_j.s1); gs += sum_j (alpha_j w_j) E_j ----
__global__ void k_wgs() {
    __shared__ float s_sh[FF];
    __shared__ float vsh[64];
    int t = threadIdx.x, lane = t & 31, w = t >> 5;
    int rowbase = blockIdx.x * 64;
    s_sh[t] = g_s[FF + t];
    __syncthreads();
#pragma unroll
    for (int rr = 0; rr < 8; rr++) {
        int r = w * 8 + rr;
        int row = rowbase + r;
        const float* er = &g_E[row * FF];
        float d = 0.f;
#pragma unroll
        for (int u = 0; u < 8; u++) { int c = lane + 32 * u; d += er[c] * s_sh[c]; }
#pragma unroll
        for (int o = 16; o > 0; o >>= 1) d += __shfl_xor_sync(0xffffffffu, d, o);
        if (lane == 0) {
            float al = g_alpha[row];
            float wj = al * d;
            g_d[row] = wj;
            vsh[r] = al * wj;
        }
    }
    __syncthreads();
    float gsp = 0.f;
#pragma unroll 4
    for (int j = 0; j < 64; j++)
        gsp += vsh[j] * g_E[(rowbase + j) * FF + t];
    atomicAdd(&g_gs[t], gsp);
}

// ---- iter1 pass 3: out_j = [w_j + alpha_j (E_j.gs)/N - w_j^2/N] / N ----
__global__ void k_out(float* __restrict__ out) {
    __shared__ float gs_sh[FF];
    int t = threadIdx.x, lane = t & 31, w = t >> 5;
    const float inv = 1.0f / (float)NN;
    gs_sh[t] = g_gs[t];
    __syncthreads();
#pragma unroll
    for (int rr = 0; rr < 8; rr++) {
        int row = blockIdx.x * 64 + w * 8 + rr;
        const float* er = &g_E[row * FF];
        float dgs = 0.f;
#pragma unroll
        for (int u = 0; u < 8; u++) { int c = lane + 32 * u; dgs += er[c] * gs_sh[c]; }
#pragma unroll
        for (int o = 16; o > 0; o >>= 1) dgs += __shfl_xor_sync(0xffffffffu, dgs, o);
        if (lane == 0 && row < NN - 1) {
            float wj = g_d[row];
            float al = g_alpha[row];
            out[row] = (wj + al * dgs * inv - wj * wj * inv) * inv;
        }
    }
}

extern "C" void kernel_launch(void* const* d_in, const int* in_sizes, int n_in,
                              void* d_out, int out_size) {
    const float* X      = (const float*)d_in[0];
    const float* linear = (const float*)d_in[2];
    const float* dirv   = (const float*)d_in[3];
    const float* feat   = (const float*)d_in[4];
    float* out = (float*)d_out;

    k_init<<<1025, 256>>>(X, linear, dirv, feat);
    k_prep<<<512, 256>>>(X);              // alpha0, Yt, s0
    k_syrk<<<dim3(16, 8), 256>>>();       // Gp partials (2MB)
    k_gred<<<1024, 256>>>();              // Gh
    k_update<<<128, 256>>>(X);            // E, d in-loop, r/T partials
    k_s1<<<128, 256>>>();                 // alpha1 + s1
    k_wgs<<<128, 256>>>();                // w + gs = G1 s1 (GEMM-free)
    k_out<<<128, 256>>>(out);             // fused output
}

// round 12
// speedup vs baseline: 1.1286x; 1.1286x over previous
#include <cuda_runtime.h>
#include <cuda_bf16.h>
#include <cstdint>

#define NN 8192
#define FF 256

// ---- device scratch ----
__device__ __align__(16) float g_E[NN * FF];             // emb after iter0 (fp32)
__device__ __align__(16) __nv_bfloat16 g_Yt[FF * NN];    // Y^T bf16 (iter0 only)
__device__ __align__(16) float g_Gp[32 * FF * FF];       // SYRK split-K partials
__device__ __align__(16) __nv_bfloat16 g_Gh[FF * FF];    // Gram bf16 (iter0)
__device__ __align__(16) float g_s[2 * FF];              // colsum(Y) per iter
__device__ __align__(16) float g_gs[FF];                 // gs = G1 s1 accum (iter1)
__device__ float g_r[NN];                                // per-row sumsq (iter0)
__device__ float g_rp[2 * NN];                           // per-row sumsq partials (iter1)
__device__ float g_alpha[NN];                            // per-row scale (alpha0 then alpha1)
__device__ float g_d[NN];                                // w_j (iter1)
__device__ float g_Tp1[1024];                            // T partials iter0
__device__ float g_Tp2[128];                             // T partials iter1
__device__ float g_ab[4];                                // a0,b0,a1,b1

// ---- mma / ldmatrix helpers ----
__device__ __forceinline__ uint32_t smem_u32(const void* p) {
    return (uint32_t)__cvta_generic_to_shared(p);
}
__device__ __forceinline__ void ldsm4(uint32_t (&r)[4], uint32_t addr) {
    asm volatile("ldmatrix.sync.aligned.m8n8.x4.shared.b16 {%0,%1,%2,%3}, [%4];"
                 : "=r"(r[0]), "=r"(r[1]), "=r"(r[2]), "=r"(r[3]) : "r"(addr));
}
__device__ __forceinline__ void ldsm4t(uint32_t (&r)[4], uint32_t addr) {
    asm volatile("ldmatrix.sync.aligned.m8n8.x4.trans.shared.b16 {%0,%1,%2,%3}, [%4];"
                 : "=r"(r[0]), "=r"(r[1]), "=r"(r[2]), "=r"(r[3]) : "r"(addr));
}
__device__ __forceinline__ void mma16816(float* c, const uint32_t* a, uint32_t b0, uint32_t b1) {
    asm volatile("mma.sync.aligned.m16n8k16.row.col.f32.bf16.bf16.f32 "
                 "{%0,%1,%2,%3}, {%4,%5,%6,%7}, {%8,%9}, {%0,%1,%2,%3};"
                 : "+f"(c[0]), "+f"(c[1]), "+f"(c[2]), "+f"(c[3])
                 : "r"(a[0]), "r"(a[1]), "r"(a[2]), "r"(a[3]), "r"(b0), "r"(b1));
}

// ---- K0: rownorm partials (blocks 0..1023) + scalars/zeroing (block 1024) ----
__global__ void k_init(const float* __restrict__ X,
                       const float* __restrict__ linear,
                       const float* __restrict__ dirv,
                       const float* __restrict__ feat) {
    int t = threadIdx.x;
    if (blockIdx.x == 1024) {
        g_s[t] = 0.f; g_s[FF + t] = 0.f; g_gs[t] = 0.f;
        __shared__ float red[256];
        for (int i = 0; i < 2; i++) {
            float pa = feat[i * FF + t] * linear[i * FF + t];
            float pb = dirv[i * FF + t] * linear[i * FF + t];
            red[t] = pa; __syncthreads();
            for (int o = 128; o > 0; o >>= 1) { if (t < o) red[t] += red[t + o]; __syncthreads(); }
            if (t == 0) g_ab[2 * i] = red[0];
            __syncthreads();
            red[t] = pb; __syncthreads();
            for (int o = 128; o > 0; o >>= 1) { if (t < o) red[t] += red[t + o]; __syncthreads(); }
            if (t == 0) g_ab[2 * i + 1] = red[0];
            __syncthreads();
        }
        return;
    }
    int warp = t >> 5, lane = t & 31;
    int row = blockIdx.x * 8 + warp;
    const float* xr = X + row * FF;
    float s = 0.f;
#pragma unroll
    for (int u = 0; u < 8; u++) { float v = xr[lane + 32 * u]; s += v * v; }
#pragma unroll
    for (int o = 16; o > 0; o >>= 1) s += __shfl_xor_sync(0xffffffffu, s, o);
    __shared__ float ws[8];
    if (lane == 0) { ws[warp] = s; g_r[row] = s; }
    __syncthreads();
    if (t == 0) {
        float tt = 0.f;
        for (int w = 0; w < 8; w++) tt += ws[w];
        g_Tp1[blockIdx.x] = tt;
    }
}

// ---- prep (iter0): T reduce + alpha0 inline; Yt = bf16(alpha0*X); colsum s0 ----
__global__ void k_prep(const float* __restrict__ src) {
    __shared__ float red[256];
    __shared__ float sh[64][65];
    __shared__ float csm[64];
    int t = threadIdx.x;
    float tacc = 0.f;
    for (int i = t; i < 1024; i += 256) tacc += g_Tp1[i];
    red[t] = tacc; __syncthreads();
    for (int o = 128; o > 0; o >>= 1) { if (t < o) red[t] += red[t + o]; __syncthreads(); }
    float T = red[0];
    __syncthreads();

    float a = g_ab[0], bb = g_ab[1];
    float nf = sqrtf(T);
    float sb = (bb >= 0.f) ? 1.f : -1.f;

    int jt = blockIdx.x >> 2;
    int cb = (blockIdx.x & 3) * 64;
    int j0 = jt * 64;
    if (t < 64) csm[t] = 0.f;
    __syncthreads();
    int lr = t >> 4, lc = (t & 15) * 4;
    float ca0 = 0, ca1 = 0, ca2 = 0, ca3 = 0;
#pragma unroll
    for (int w = 0; w < 4; w++) {
        int row = lr + w * 16;
        int J = j0 + row;
        float inner = a * sb * g_r[J] / nf;
        float scale = (inner <= 0.f) ? inner : 0.f;
        float al = a - scale * sb / nf;
        if ((blockIdx.x & 3) == 0 && (t & 15) == 0) g_alpha[J] = al;
        float4 v = *(const float4*)&src[J * FF + cb + lc];
        float y0 = al * v.x, y1 = al * v.y, y2 = al * v.z, y3 = al * v.w;
        sh[row][lc] = y0; sh[row][lc + 1] = y1; sh[row][lc + 2] = y2; sh[row][lc + 3] = y3;
        ca0 += y0; ca1 += y1; ca2 += y2; ca3 += y3;
    }
    atomicAdd(&csm[lc], ca0); atomicAdd(&csm[lc + 1], ca1);
    atomicAdd(&csm[lc + 2], ca2); atomicAdd(&csm[lc + 3], ca3);
    __syncthreads();
    int cl = t >> 4, jl = (t & 15) * 4;
#pragma unroll
    for (int w = 0; w < 4; w++) {
        int c = cl + w * 16;
        __nv_bfloat16 p[4];
        p[0] = __float2bfloat16(sh[jl + 0][c]);
        p[1] = __float2bfloat16(sh[jl + 1][c]);
        p[2] = __float2bfloat16(sh[jl + 2][c]);
        p[3] = __float2bfloat16(sh[jl + 3][c]);
        *(uint2*)&g_Yt[(cb + c) * NN + j0 + jl] = *(uint2*)p;
    }
    if (t < 64) atomicAdd(&g_s[cb + t], csm[t]);
}

// ---- SYRK: 128x128 tiles x 32 chunks of 256 rows; grid (4,32) ----
__global__ __launch_bounds__(256, 2) void k_syrk() {
    __shared__ __nv_bfloat16 Ash[128][72];
    __shared__ __nv_bfloat16 Bsh[128][72];
    int t = threadIdx.x, lane = t & 31, w = t >> 5;
    int wm = w >> 2, wn = w & 3;
    int pa = blockIdx.x >> 1, pb = blockIdx.x & 1;
    int j0 = blockIdx.y * 256;
    float acc[4][4][4];
#pragma unroll
    for (int i = 0; i < 4; i++)
#pragma unroll
        for (int j = 0; j < 4; j++)
#pragma unroll
            for (int q = 0; q < 4; q++) acc[i][j][q] = 0.f;

    for (int ks = 0; ks < 4; ks++) {
        __syncthreads();
#pragma unroll
        for (int u = 0; u < 4; u++) {
            int idx = t + u * 256;
            int row = idx >> 3, g = idx & 7;
            *(uint4*)&Ash[row][g * 8] = *(const uint4*)&g_Yt[(pa * 128 + row) * NN + j0 + ks * 64 + g * 8];
            *(uint4*)&Bsh[row][g * 8] = *(const uint4*)&g_Yt[(pb * 128 + row) * NN + j0 + ks * 64 + g * 8];
        }
        __syncthreads();
#pragma unroll
        for (int kk = 0; kk < 4; kk++) {
            uint32_t a[4][4], b[2][4];
#pragma unroll
            for (int mi = 0; mi < 4; mi++) {
                int row = wm * 64 + mi * 16 + (lane & 15);
                int col = kk * 16 + 8 * (lane >> 4);
                ldsm4(a[mi], smem_u32(&Ash[row][col]));
            }
#pragma unroll
            for (int p = 0; p < 2; p++) {
                int g = lane >> 3;
                int row = wn * 32 + p * 16 + 8 * (g >> 1) + (lane & 7);
                int col = kk * 16 + 8 * (g & 1);
                ldsm4(b[p], smem_u32(&Bsh[row][col]));
            }
#pragma unroll
            for (int mi = 0; mi < 4; mi++)
#pragma unroll
                for (int nj = 0; nj < 4; nj++)
                    mma16816(acc[mi][nj], a[mi], b[nj >> 1][(nj & 1) * 2], b[nj >> 1][(nj & 1) * 2 + 1]);
        }
    }
    float* gp = &g_Gp[blockIdx.y * (FF * FF)];
#pragma unroll
    for (int mi = 0; mi < 4; mi++)
#pragma unroll
        for (int nj = 0; nj < 4; nj++)
#pragma unroll
            for (int gi = 0; gi < 2; gi++) {
                int row = pa * 128 + wm * 64 + mi * 16 + (lane >> 2) + 8 * gi;
                int col = pb * 128 + wn * 32 + nj * 8 + (lane & 3) * 2;
                *(float2*)&gp[row * FF + col] = make_float2(acc[mi][nj][2 * gi], acc[mi][nj][2 * gi + 1]);
            }
}

// ---- Gp reduce -> Gh; 1 output/thread, 32 chunks in 4 explicit 8-wide batches ----
__global__ void k_gred() {
    int i = blockIdx.x * 256 + threadIdx.x;
    float sum = 0.f;
#pragma unroll
    for (int batch = 0; batch < 4; batch++) {
        float v[8];
#pragma unroll
        for (int q = 0; q < 8; q++) v[q] = g_Gp[(batch * 8 + q) * (FF * FF) + i];
#pragma unroll
        for (int q = 0; q < 8; q++) sum += v[q];
    }
    g_Gh[i] = __float2bfloat16(sum);
}

// ---- update (iter0): E = y + (Y.Gh - d*y)/N; d = Y.s in-loop; r/T partials ----
__global__ __launch_bounds__(256, 2) void k_update(const float* __restrict__ src) {
    __shared__ __nv_bfloat16 Ysh[16][136];
    __shared__ __nv_bfloat16 Gsh[128][24];
    __shared__ float s_sh[FF];
    __shared__ float dps[256];
    __shared__ float rsm[128];
    int t = threadIdx.x, lane = t & 31, w = t >> 5;
    int wm = w >> 2, wn = w & 3;
    int rt = blockIdx.x >> 1, ct = blockIdx.x & 1;
    int rowbase = rt * 128, colbase = ct * 128;
    if (t < 128) rsm[t] = 0.f;
    s_sh[t] = g_s[t];
    float dpart = 0.f;
    int dj = t & 127, dhalf = t >> 7;
    float acc[4][4][4];
#pragma unroll
    for (int i = 0; i < 4; i++)
#pragma unroll
        for (int j = 0; j < 4; j++)
#pragma unroll
            for (int q = 0; q < 4; q++) acc[i][j][q] = 0.f;

    for (int kk = 0; kk < 16; kk++) {
        __syncthreads();
        {
            int row = t >> 4, g = t & 15;
            *(uint4*)&Ysh[row][g * 8] = *(const uint4*)&g_Yt[(kk * 16 + row) * NN + rowbase + g * 8];
        }
        {
            int n = t >> 1, g = t & 1;
            *(uint4*)&Gsh[n][g * 8] = *(const uint4*)&g_Gh[(colbase + n) * FF + kk * 16 + g * 8];
        }
        __syncthreads();
#pragma unroll
        for (int ff = 0; ff < 8; ff++) {
            int f = dhalf * 8 + ff;
            dpart += __bfloat162float(Ysh[f][dj]) * s_sh[kk * 16 + f];
        }
        uint32_t a[4][4], b[2][4];
#pragma unroll
        for (int mi = 0; mi < 4; mi++) {
            int krow = (lane & 7) + 8 * ((lane >> 4) & 1);
            int mcol = wm * 64 + mi * 16 + 8 * ((lane >> 3) & 1);
            ldsm4t(a[mi], smem_u32(&Ysh[krow][mcol]));
        }
#pragma unroll
        for (int p = 0; p < 2; p++) {
            int g = lane >> 3;
            int row = wn * 32 + p * 16 + 8 * (g >> 1) + (lane & 7);
            int col = 8 * (g & 1);
            ldsm4(b[p], smem_u32(&Gsh[row][col]));
        }
#pragma unroll
        for (int mi = 0; mi < 4; mi++)
#pragma unroll
            for (int nj = 0; nj < 4; nj++)
                mma16816(acc[mi][nj], a[mi], b[nj >> 1][(nj & 1) * 2], b[nj >> 1][(nj & 1) * 2 + 1]);
    }
    dps[t] = dpart;
    __syncthreads();

    const float inv = 1.0f / (float)NN;
    float rowsq[4][2];
#pragma unroll
    for (int i = 0; i < 4; i++) { rowsq[i][0] = 0.f; rowsq[i][1] = 0.f; }

#pragma unroll
    for (int mi = 0; mi < 4; mi++)
#pragma unroll
        for (int gi = 0; gi < 2; gi++) {
            int r = wm * 64 + mi * 16 + (lane >> 2) + 8 * gi;
            int Rg = rowbase + r;
            float al = g_alpha[Rg];
            float dd = dps[r] + dps[r + 128];
#pragma unroll
            for (int nj = 0; nj < 4; nj++) {
                int c = colbase + wn * 32 + nj * 8 + (lane & 3) * 2;
                float2 v = *(const float2*)&src[Rg * FF + c];
                float y0 = al * v.x, y1 = al * v.y;
                float e0 = y0 + (acc[mi][nj][2 * gi] - dd * y0) * inv;
                float e1 = y1 + (acc[mi][nj][2 * gi + 1] - dd * y1) * inv;
                *(float2*)&g_E[Rg * FF + c] = make_float2(e0, e1);
                rowsq[mi][gi] += e0 * e0 + e1 * e1;
            }
        }
#pragma unroll
    for (int mi = 0; mi < 4; mi++)
#pragma unroll
        for (int gi = 0; gi < 2; gi++) {
            float v = rowsq[mi][gi];
            v += __shfl_xor_sync(0xffffffffu, v, 1);
            v += __shfl_xor_sync(0xffffffffu, v, 2);
            if ((lane & 3) == 0) atomicAdd(&rsm[wm * 64 + mi * 16 + (lane >> 2) + 8 * gi], v);
        }
    __syncthreads();
    if (t < 128) g_rp[ct * NN + rowbase + t] = rsm[t];
    if (t == 0) {
        float tt = 0.f;
        for (int i = 0; i < 128; i++) tt += rsm[i];
        g_Tp2[blockIdx.x] = tt;
    }
}

// ---- iter1 pass 1 (256 blocks, 32 rows): alpha1 + s1 partial colsum ----
__global__ void k_s1() {
    __shared__ float red[256];
    __shared__ float ash[32];
    int t = threadIdx.x;
    float tacc = (t < 128) ? g_Tp2[t] : 0.f;
    red[t] = tacc; __syncthreads();
    for (int o = 128; o > 0; o >>= 1) { if (t < o) red[t] += red[t + o]; __syncthreads(); }
    float T = red[0];
    float a = g_ab[2], bb = g_ab[3];
    float nf = sqrtf(T);
    float sb = (bb >= 0.f) ? 1.f : -1.f;
    int rowbase = blockIdx.x * 32;
    if (t < 32) {
        int J = rowbase + t;
        float rJ = g_rp[J] + g_rp[NN + J];
        float inner = a * sb * rJ / nf;
        float scale = (inner <= 0.f) ? inner : 0.f;
        float al = a - scale * sb / nf;
        g_alpha[J] = al;
        ash[t] = al;
    }
    __syncthreads();
    float cs = 0.f;
#pragma unroll
    for (int j = 0; j < 32; j++)
        cs += ash[j] * g_E[(rowbase + j) * FF + t];
    atomicAdd(&g_s[FF + t], cs);
}

// ---- iter1 pass 2 (256 blocks, 32 rows): w_j; gs += (alpha_j w_j) E_j ----
__global__ void k_wgs() {
    __shared__ float s_sh[FF];
    __shared__ float vsh[32];
    int t = threadIdx.x, lane = t & 31, w = t >> 5;
    int rowbase = blockIdx.x * 32;
    s_sh[t] = g_s[FF + t];
    __syncthreads();
#pragma unroll
    for (int rr = 0; rr < 4; rr++) {
        int r = w * 4 + rr;
        int row = rowbase + r;
        const float* er = &g_E[row * FF];
        float d = 0.f;
#pragma unroll
        for (int u = 0; u < 8; u++) { int c = lane + 32 * u; d += er[c] * s_sh[c]; }
#pragma unroll
        for (int o = 16; o > 0; o >>= 1) d += __shfl_xor_sync(0xffffffffu, d, o);
        if (lane == 0) {
            float al = g_alpha[row];
            float wj = al * d;
            g_d[row] = wj;
            vsh[r] = al * wj;
        }
    }
    __syncthreads();
    float gsp = 0.f;
#pragma unroll
    for (int j = 0; j < 32; j++)
        gsp += vsh[j] * g_E[(rowbase + j) * FF + t];
    atomicAdd(&g_gs[t], gsp);
}

// ---- iter1 pass 3 (512 blocks, 16 rows): out_j = [w + al*(E.gs)/N - w^2/N]/N ----
__global__ void k_out(float* __restrict__ out) {
    __shared__ float gs_sh[FF];
    int t = threadIdx.x, lane = t & 31, w = t >> 5;
    const float inv = 1.0f / (float)NN;
    gs_sh[t] = g_gs[t];
    __syncthreads();
#pragma unroll
    for (int rr = 0; rr < 2; rr++) {
        int row = blockIdx.x * 16 + w * 2 + rr;
        const float* er = &g_E[row * FF];
        float dgs = 0.f;
#pragma unroll
        for (int u = 0; u < 8; u++) { int c = lane + 32 * u; dgs += er[c] * gs_sh[c]; }
#pragma unroll
        for (int o = 16; o > 0; o >>= 1) dgs += __shfl_xor_sync(0xffffffffu, dgs, o);
        if (lane == 0 && row < NN - 1) {
            float wj = g_d[row];
            float al = g_alpha[row];
            out[row] = (wj + al * dgs * inv - wj * wj * inv) * inv;
        }
    }
}

extern "C" void kernel_launch(void* const* d_in, const int* in_sizes, int n_in,
                              void* d_out, int out_size) {
    const float* X      = (const float*)d_in[0];
    const float* linear = (const float*)d_in[2];
    const float* dirv   = (const float*)d_in[3];
    const float* feat   = (const float*)d_in[4];
    float* out = (float*)d_out;

    k_init<<<1025, 256>>>(X, linear, dirv, feat);
    k_prep<<<512, 256>>>(X);              // alpha0, Yt, s0
    k_syrk<<<dim3(4, 32), 256>>>();       // Gp partials (proven 128x128 tiling)
    k_gred<<<256, 256>>>();               // Gh (forced MLP-8 batches)
    k_update<<<128, 256>>>(X);            // E, d in-loop, r/T partials
    k_s1<<<256, 256>>>();                 // alpha1 + s1
    k_wgs<<<256, 256>>>();                // w + gs = G1 s1 (GEMM-free)
    k_out<<<512, 256>>>(out);             // fused output
}

// round 14
// speedup vs baseline: 1.1293x; 1.0006x over previous
#include <cuda_runtime.h>
#include <cuda_bf16.h>
#include <cstdint>

#define NN 8192
#define FF 256

// ---- device scratch ----
__device__ __align__(16) float g_E[NN * FF];             // emb after iter0 (fp32)
__device__ __align__(16) __nv_bfloat16 g_Yt[FF * NN];    // Y^T bf16 (iter0 only)
__device__ __align__(16) float g_Gp[32 * FF * FF];       // SYRK split-K partials
__device__ __align__(16) __nv_bfloat16 g_Gh[FF * FF];    // Gram bf16 (iter0)
__device__ __align__(16) float g_s[2 * FF];              // colsum(Y) per iter
__device__ __align__(16) float g_gs[FF];                 // gs = G1 s1 accum (iter1)
__device__ float g_r[NN];                                // per-row sumsq (iter0)
__device__ float g_rp[2 * NN];                           // per-row sumsq partials (iter1)
__device__ float g_alpha[NN];                            // per-row scale (alpha0 then alpha1)
__device__ float g_d[NN];                                // w_j (iter1)
__device__ float g_Tp1[1024];                            // T partials iter0
__device__ float g_Tp2[128];                             // T partials iter1
__device__ float g_ab[4];                                // a0,b0,a1,b1

// ---- mma / ldmatrix helpers ----
__device__ __forceinline__ uint32_t smem_u32(const void* p) {
    return (uint32_t)__cvta_generic_to_shared(p);
}
__device__ __forceinline__ void ldsm4(uint32_t (&r)[4], uint32_t addr) {
    asm volatile("ldmatrix.sync.aligned.m8n8.x4.shared.b16 {%0,%1,%2,%3}, [%4];"
                 : "=r"(r[0]), "=r"(r[1]), "=r"(r[2]), "=r"(r[3]) : "r"(addr));
}
__device__ __forceinline__ void ldsm4t(uint32_t (&r)[4], uint32_t addr) {
    asm volatile("ldmatrix.sync.aligned.m8n8.x4.trans.shared.b16 {%0,%1,%2,%3}, [%4];"
                 : "=r"(r[0]), "=r"(r[1]), "=r"(r[2]), "=r"(r[3]) : "r"(addr));
}
__device__ __forceinline__ void mma16816(float* c, const uint32_t* a, uint32_t b0, uint32_t b1) {
    asm volatile("mma.sync.aligned.m16n8k16.row.col.f32.bf16.bf16.f32 "
                 "{%0,%1,%2,%3}, {%4,%5,%6,%7}, {%8,%9}, {%0,%1,%2,%3};"
                 : "+f"(c[0]), "+f"(c[1]), "+f"(c[2]), "+f"(c[3])
                 : "r"(a[0]), "r"(a[1]), "r"(a[2]), "r"(a[3]), "r"(b0), "r"(b1));
}

// ---- K0: rownorm partials (blocks 0..1023) + scalars/zeroing (block 1024) ----
__global__ void k_init(const float* __restrict__ X,
                       const float* __restrict__ linear,
                       const float* __restrict__ dirv,
                       const float* __restrict__ feat) {
    int t = threadIdx.x;
    if (blockIdx.x == 1024) {
        g_s[t] = 0.f; g_s[FF + t] = 0.f; g_gs[t] = 0.f;
        __shared__ float red[256];
        for (int i = 0; i < 2; i++) {
            float pa = feat[i * FF + t] * linear[i * FF + t];
            float pb = dirv[i * FF + t] * linear[i * FF + t];
            red[t] = pa; __syncthreads();
            for (int o = 128; o > 0; o >>= 1) { if (t < o) red[t] += red[t + o]; __syncthreads(); }
            if (t == 0) g_ab[2 * i] = red[0];
            __syncthreads();
            red[t] = pb; __syncthreads();
            for (int o = 128; o > 0; o >>= 1) { if (t < o) red[t] += red[t + o]; __syncthreads(); }
            if (t == 0) g_ab[2 * i + 1] = red[0];
            __syncthreads();
        }
        return;
    }
    int warp = t >> 5, lane = t & 31;
    int row = blockIdx.x * 8 + warp;
    const float* xr = X + row * FF;
    float s = 0.f;
#pragma unroll
    for (int u = 0; u < 8; u++) { float v = xr[lane + 32 * u]; s += v * v; }
#pragma unroll
    for (int o = 16; o > 0; o >>= 1) s += __shfl_xor_sync(0xffffffffu, s, o);
    __shared__ float ws[8];
    if (lane == 0) { ws[warp] = s; g_r[row] = s; }
    __syncthreads();
    if (t == 0) {
        float tt = 0.f;
        for (int w = 0; w < 8; w++) tt += ws[w];
        g_Tp1[blockIdx.x] = tt;
    }
}

// ---- prep (iter0): T reduce + alpha0 inline; Yt = bf16(alpha0*X); colsum s0 ----
__global__ void k_prep(const float* __restrict__ src) {
    __shared__ float red[256];
    __shared__ float sh[64][65];
    __shared__ float csm[64];
    int t = threadIdx.x;
    float tacc = 0.f;
    for (int i = t; i < 1024; i += 256) tacc += g_Tp1[i];
    red[t] = tacc; __syncthreads();
    for (int o = 128; o > 0; o >>= 1) { if (t < o) red[t] += red[t + o]; __syncthreads(); }
    float T = red[0];
    __syncthreads();

    float a = g_ab[0], bb = g_ab[1];
    float nf = sqrtf(T);
    float sb = (bb >= 0.f) ? 1.f : -1.f;

    int jt = blockIdx.x >> 2;
    int cb = (blockIdx.x & 3) * 64;
    int j0 = jt * 64;
    if (t < 64) csm[t] = 0.f;
    __syncthreads();
    int lr = t >> 4, lc = (t & 15) * 4;
    float ca0 = 0, ca1 = 0, ca2 = 0, ca3 = 0;
#pragma unroll
    for (int w = 0; w < 4; w++) {
        int row = lr + w * 16;
        int J = j0 + row;
        float inner = a * sb * g_r[J] / nf;
        float scale = (inner <= 0.f) ? inner : 0.f;
        float al = a - scale * sb / nf;
        if ((blockIdx.x & 3) == 0 && (t & 15) == 0) g_alpha[J] = al;
        float4 v = *(const float4*)&src[J * FF + cb + lc];
        float y0 = al * v.x, y1 = al * v.y, y2 = al * v.z, y3 = al * v.w;
        sh[row][lc] = y0; sh[row][lc + 1] = y1; sh[row][lc + 2] = y2; sh[row][lc + 3] = y3;
        ca0 += y0; ca1 += y1; ca2 += y2; ca3 += y3;
    }
    atomicAdd(&csm[lc], ca0); atomicAdd(&csm[lc + 1], ca1);
    atomicAdd(&csm[lc + 2], ca2); atomicAdd(&csm[lc + 3], ca3);
    __syncthreads();
    int cl = t >> 4, jl = (t & 15) * 4;
#pragma unroll
    for (int w = 0; w < 4; w++) {
        int c = cl + w * 16;
        __nv_bfloat16 p[4];
        p[0] = __float2bfloat16(sh[jl + 0][c]);
        p[1] = __float2bfloat16(sh[jl + 1][c]);
        p[2] = __float2bfloat16(sh[jl + 2][c]);
        p[3] = __float2bfloat16(sh[jl + 3][c]);
        *(uint2*)&g_Yt[(cb + c) * NN + j0 + jl] = *(uint2*)p;
    }
    if (t < 64) atomicAdd(&g_s[cb + t], csm[t]);
}

// ---- SYRK: 128x128 tiles x 32 chunks of 256 rows; grid (4,32) ----
__global__ __launch_bounds__(256, 2) void k_syrk() {
    __shared__ __nv_bfloat16 Ash[128][72];
    __shared__ __nv_bfloat16 Bsh[128][72];
    int t = threadIdx.x, lane = t & 31, w = t >> 5;
    int wm = w >> 2, wn = w & 3;
    int pa = blockIdx.x >> 1, pb = blockIdx.x & 1;
    int j0 = blockIdx.y * 256;
    float acc[4][4][4];
#pragma unroll
    for (int i = 0; i < 4; i++)
#pragma unroll
        for (int j = 0; j < 4; j++)
#pragma unroll
            for (int q = 0; q < 4; q++) acc[i][j][q] = 0.f;

    for (int ks = 0; ks < 4; ks++) {
        __syncthreads();
#pragma unroll
        for (int u = 0; u < 4; u++) {
            int idx = t + u * 256;
            int row = idx >> 3, g = idx & 7;
            *(uint4*)&Ash[row][g * 8] = *(const uint4*)&g_Yt[(pa * 128 + row) * NN + j0 + ks * 64 + g * 8];
            *(uint4*)&Bsh[row][g * 8] = *(const uint4*)&g_Yt[(pb * 128 + row) * NN + j0 + ks * 64 + g * 8];
        }
        __syncthreads();
#pragma unroll
        for (int kk = 0; kk < 4; kk++) {
            uint32_t a[4][4], b[2][4];
#pragma unroll
            for (int mi = 0; mi < 4; mi++) {
                int row = wm * 64 + mi * 16 + (lane & 15);
                int col = kk * 16 + 8 * (lane >> 4);
                ldsm4(a[mi], smem_u32(&Ash[row][col]));
            }
#pragma unroll
            for (int p = 0; p < 2; p++) {
                int g = lane >> 3;
                int row = wn * 32 + p * 16 + 8 * (g >> 1) + (lane & 7);
                int col = kk * 16 + 8 * (g & 1);
                ldsm4(b[p], smem_u32(&Bsh[row][col]));
            }
#pragma unroll
            for (int mi = 0; mi < 4; mi++)
#pragma unroll
                for (int nj = 0; nj < 4; nj++)
                    mma16816(acc[mi][nj], a[mi], b[nj >> 1][(nj & 1) * 2], b[nj >> 1][(nj & 1) * 2 + 1]);
        }
    }
    float* gp = &g_Gp[blockIdx.y * (FF * FF)];
#pragma unroll
    for (int mi = 0; mi < 4; mi++)
#pragma unroll
        for (int nj = 0; nj < 4; nj++)
#pragma unroll
            for (int gi = 0; gi < 2; gi++) {
                int row = pa * 128 + wm * 64 + mi * 16 + (lane >> 2) + 8 * gi;
                int col = pb * 128 + wn * 32 + nj * 8 + (lane & 3) * 2;
                *(float2*)&gp[row * FF + col] = make_float2(acc[mi][nj][2 * gi], acc[mi][nj][2 * gi + 1]);
            }
}

// ---- Gp reduce -> Gh; grid 1024, 4 threads/output x 8 chunks each (MLP 8) ----
__global__ void k_gred() {
    int t = threadIdx.x, b = blockIdx.x;
    int i = b * 64 + (t >> 2);
    int ch0 = (t & 3) * 8;
    float v[8];
#pragma unroll
    for (int q = 0; q < 8; q++) v[q] = g_Gp[(ch0 + q) * (FF * FF) + i];
    float sum = 0.f;
#pragma unroll
    for (int q = 0; q < 8; q++) sum += v[q];
    sum += __shfl_xor_sync(0xffffffffu, sum, 1);
    sum += __shfl_xor_sync(0xffffffffu, sum, 2);
    if ((t & 3) == 0) g_Gh[i] = __float2bfloat16(sum);
}

// ---- update (iter0): E = y + (Y.Gh - d*y)/N; d = Y.s in-loop; r/T partials ----
__global__ __launch_bounds__(256, 2) void k_update(const float* __restrict__ src) {
    __shared__ __nv_bfloat16 Ysh[16][136];
    __shared__ __nv_bfloat16 Gsh[128][24];
    __shared__ float s_sh[FF];
    __shared__ float dps[256];
    __shared__ float rsm[128];
    int t = threadIdx.x, lane = t & 31, w = t >> 5;
    int wm = w >> 2, wn = w & 3;
    int rt = blockIdx.x >> 1, ct = blockIdx.x & 1;
    int rowbase = rt * 128, colbase = ct * 128;
    if (t < 128) rsm[t] = 0.f;
    s_sh[t] = g_s[t];
    float dpart = 0.f;
    int dj = t & 127, dhalf = t >> 7;
    float acc[4][4][4];
#pragma unroll
    for (int i = 0; i < 4; i++)
#pragma unroll
        for (int j = 0; j < 4; j++)
#pragma unroll
            for (int q = 0; q < 4; q++) acc[i][j][q] = 0.f;

    for (int kk = 0; kk < 16; kk++) {
        __syncthreads();
        {
            int row = t >> 4, g = t & 15;
            *(uint4*)&Ysh[row][g * 8] = *(const uint4*)&g_Yt[(kk * 16 + row) * NN + rowbase + g * 8];
        }
        {
            int n = t >> 1, g = t & 1;
            *(uint4*)&Gsh[n][g * 8] = *(const uint4*)&g_Gh[(colbase + n) * FF + kk * 16 + g * 8];
        }
        __syncthreads();
#pragma unroll
        for (int ff = 0; ff < 8; ff++) {
            int f = dhalf * 8 + ff;
            dpart += __bfloat162float(Ysh[f][dj]) * s_sh[kk * 16 + f];
        }
        uint32_t a[4][4], b[2][4];
#pragma unroll
        for (int mi = 0; mi < 4; mi++) {
            int krow = (lane & 7) + 8 * ((lane >> 4) & 1);
            int mcol = wm * 64 + mi * 16 + 8 * ((lane >> 3) & 1);
            ldsm4t(a[mi], smem_u32(&Ysh[krow][mcol]));
        }
#pragma unroll
        for (int p = 0; p < 2; p++) {
            int g = lane >> 3;
            int row = wn * 32 + p * 16 + 8 * (g >> 1) + (lane & 7);
            int col = 8 * (g & 1);
            ldsm4(b[p], smem_u32(&Gsh[row][col]));
        }
#pragma unroll
        for (int mi = 0; mi < 4; mi++)
#pragma unroll
            for (int nj = 0; nj < 4; nj++)
                mma16816(acc[mi][nj], a[mi], b[nj >> 1][(nj & 1) * 2], b[nj >> 1][(nj & 1) * 2 + 1]);
    }
    dps[t] = dpart;
    __syncthreads();

    const float inv = 1.0f / (float)NN;
    float rowsq[4][2];
#pragma unroll
    for (int i = 0; i < 4; i++) { rowsq[i][0] = 0.f; rowsq[i][1] = 0.f; }

#pragma unroll
    for (int mi = 0; mi < 4; mi++)
#pragma unroll
        for (int gi = 0; gi < 2; gi++) {
            int r = wm * 64 + mi * 16 + (lane >> 2) + 8 * gi;
            int Rg = rowbase + r;
            float al = g_alpha[Rg];
            float dd = dps[r] + dps[r + 128];
#pragma unroll
            for (int nj = 0; nj < 4; nj++) {
                int c = colbase + wn * 32 + nj * 8 + (lane & 3) * 2;
                float2 v = *(const float2*)&src[Rg * FF + c];
                float y0 = al * v.x, y1 = al * v.y;
                float e0 = y0 + (acc[mi][nj][2 * gi] - dd * y0) * inv;
                float e1 = y1 + (acc[mi][nj][2 * gi + 1] - dd * y1) * inv;
                *(float2*)&g_E[Rg * FF + c] = make_float2(e0, e1);
                rowsq[mi][gi] += e0 * e0 + e1 * e1;
            }
        }
#pragma unroll
    for (int mi = 0; mi < 4; mi++)
#pragma unroll
        for (int gi = 0; gi < 2; gi++) {
            float v = rowsq[mi][gi];
            v += __shfl_xor_sync(0xffffffffu, v, 1);
            v += __shfl_xor_sync(0xffffffffu, v, 2);
            if ((lane & 3) == 0) atomicAdd(&rsm[wm * 64 + mi * 16 + (lane >> 2) + 8 * gi], v);
        }
    __syncthreads();
    if (t < 128) g_rp[ct * NN + rowbase + t] = rsm[t];
    if (t == 0) {
        float tt = 0.f;
        for (int i = 0; i < 128; i++) tt += rsm[i];
        g_Tp2[blockIdx.x] = tt;
    }
}

// ---- iter1 pass 1 (256 blocks, 32 rows): alpha1 + s1 partial colsum ----
__global__ void k_s1() {
    __shared__ float red[256];
    __shared__ float ash[32];
    int t = threadIdx.x;
    float tacc = (t < 128) ? g_Tp2[t] : 0.f;
    red[t] = tacc; __syncthreads();
    for (int o = 128; o > 0; o >>= 1) { if (t < o) red[t] += red[t + o]; __syncthreads(); }
    float T = red[0];
    float a = g_ab[2], bb = g_ab[3];
    float nf = sqrtf(T);
    float sb = (bb >= 0.f) ? 1.f : -1.f;
    int rowbase = blockIdx.x * 32;
    if (t < 32) {
        int J = rowbase + t;
        float rJ = g_rp[J] + g_rp[NN + J];
        float inner = a * sb * rJ / nf;
        float scale = (inner <= 0.f) ? inner : 0.f;
        float al = a - scale * sb / nf;
        g_alpha[J] = al;
        ash[t] = al;
    }
    __syncthreads();
    float cs = 0.f;
#pragma unroll
    for (int j = 0; j < 32; j++)
        cs += ash[j] * g_E[(rowbase + j) * FF + t];
    atomicAdd(&g_s[FF + t], cs);
}

// ---- iter1 pass 2 (256 blocks, 32 rows): w_j; gs += (alpha_j w_j) E_j ----
__global__ void k_wgs() {
    __shared__ float s_sh[FF];
    __shared__ float vsh[32];
    int t = threadIdx.x, lane = t & 31, w = t >> 5;
    int rowbase = blockIdx.x * 32;
    s_sh[t] = g_s[FF + t];
    __syncthreads();
#pragma unroll
    for (int rr = 0; rr < 4; rr++) {
        int r = w * 4 + rr;
        int row = rowbase + r;
        const float* er = &g_E[row * FF];
        float d = 0.f;
#pragma unroll
        for (int u = 0; u < 8; u++) { int c = lane + 32 * u; d += er[c] * s_sh[c]; }
#pragma unroll
        for (int o = 16; o > 0; o >>= 1) d += __shfl_xor_sync(0xffffffffu, d, o);
        if (lane == 0) {
            float al = g_alpha[row];
            float wj = al * d;
            g_d[row] = wj;
            vsh[r] = al * wj;
        }
    }
    __syncthreads();
    float gsp = 0.f;
#pragma unroll
    for (int j = 0; j < 32; j++)
        gsp += vsh[j] * g_E[(rowbase + j) * FF + t];
    atomicAdd(&g_gs[t], gsp);
}

// ---- iter1 pass 3 (512 blocks, 16 rows): out_j = [w + al*(E.gs)/N - w^2/N]/N ----
__global__ void k_out(float* __restrict__ out) {
    __shared__ float gs_sh[FF];
    int t = threadIdx.x, lane = t & 31, w = t >> 5;
    const float inv = 1.0f / (float)NN;
    gs_sh[t] = g_gs[t];
    __syncthreads();
#pragma unroll
    for (int rr = 0; rr < 2; rr++) {
        int row = blockIdx.x * 16 + w * 2 + rr;
        const float* er = &g_E[row * FF];
        float dgs = 0.f;
#pragma unroll
        for (int u = 0; u < 8; u++) { int c = lane + 32 * u; dgs += er[c] * gs_sh[c]; }
#pragma unroll
        for (int o = 16; o > 0; o >>= 1) dgs += __shfl_xor_sync(0xffffffffu, dgs, o);
        if (lane == 0 && row < NN - 1) {
            float wj = g_d[row];
            float al = g_alpha[row];
            out[row] = (wj + al * dgs * inv - wj * wj * inv) * inv;
        }
    }
}

extern "C" void kernel_launch(void* const* d_in, const int* in_sizes, int n_in,
                              void* d_out, int out_size) {
    const float* X      = (const float*)d_in[0];
    const float* linear = (const float*)d_in[2];
    const float* dirv   = (const float*)d_in[3];
    const float* feat   = (const float*)d_in[4];
    float* out = (float*)d_out;

    k_init<<<1025, 256>>>(X, linear, dirv, feat);
    k_prep<<<512, 256>>>(X);              // alpha0, Yt, s0
    k_syrk<<<dim3(4, 32), 256>>>();       // Gp partials (proven 128x128 tiling)
    k_gred<<<1024, 256>>>();              // Gh (1024 blocks x MLP-8)
    k_update<<<128, 256>>>(X);            // E, d in-loop, r/T partials
    k_s1<<<256, 256>>>();                 // alpha1 + s1
    k_wgs<<<256, 256>>>();                // w + gs = G1 s1 (GEMM-free)
    k_out<<<512, 256>>>(out);             // fused output
}